// round 11
// baseline (speedup 1.0000x reference)
#include <cuda_runtime.h>
#include <math.h>
#include <stdint.h>

// Problem constants
#define BATCH   8
#define SEQ     2048
#define HID     1024
#define NPB     (SEQ * HID)        // 2,097,152 elements per batch
#define VEC_PB  (NPB / 4)          // 524,288 float4 per batch
#define TOTALV  (BATCH * VEC_PB)   // 4,194,304 float4 total
#define RANK0   1048576u           // 0-indexed ascending rank of threshold (N - k)
#define HBLK    128                // hist blocks per batch (16 rows each)
#define FBLK    256                // final blocks per batch (8 rows each)

// Static scratch (no runtime allocation; zero-initialized at module load;
// every kernel run restores the zero/reset state it consumed)
__device__ unsigned g_hist[2][BATCH][2048];
__device__ unsigned g_d0[BATCH];      // selected digit, pass 0
__device__ unsigned g_r1[BATCH];      // remaining rank after pass 0
__device__ float    g_thr[BATCH];
__device__ unsigned g_done0, g_done1; // last-block-done counters

__device__ __forceinline__ float sigmoidf_fast(float x) {
    return 1.0f / (1.0f + __expf(-x));
}

// band(t): 0 for t<128, else floor(log2(t>>7)) + 1   (T=2048, L=4)
__device__ __forceinline__ int band_of(int t) {
    return (t >= 128) ? (32 - __clz(t >> 7)) : 0;
}

// per-thread importance vector for 4 consecutive dims d..d+3 of one band
__device__ __forceinline__ float4 imp4_of(const float* __restrict__ bi,
                                          const float* __restrict__ di,
                                          int band, int d) {
    float4 r;
    r.x = sigmoidf_fast(__ldg(&bi[band * HID + d + 0])) * sigmoidf_fast(__ldg(&di[d + 0]));
    r.y = sigmoidf_fast(__ldg(&bi[band * HID + d + 1])) * sigmoidf_fast(__ldg(&di[d + 1]));
    r.z = sigmoidf_fast(__ldg(&bi[band * HID + d + 2])) * sigmoidf_fast(__ldg(&di[d + 2]));
    r.w = sigmoidf_fast(__ldg(&bi[band * HID + d + 3])) * sigmoidf_fast(__ldg(&di[d + 3]));
    return r;
}

// ---------------------------------------------------------------------------
// warp-collective digit select over a 32*PER-bin histogram (L2-coherent reads:
// the histogram was produced by other blocks' global atomics this launch).
// ---------------------------------------------------------------------------
template <int PER>
__device__ __forceinline__ unsigned warp_select(const unsigned* __restrict__ h,
                                                unsigned rank, unsigned* rem) {
    const int lane = threadIdx.x & 31;
    unsigned s = 0;
    #pragma unroll
    for (int j = 0; j < PER; j++) s += __ldcg(&h[lane * PER + j]);

    unsigned v = s;
    #pragma unroll
    for (int o = 1; o < 32; o <<= 1) {
        unsigned t = __shfl_up_sync(0xFFFFFFFFu, v, o);
        if (lane >= o) v += t;
    }
    unsigned excl = v - s;

    bool in = (rank >= excl) && (rank < excl + s);
    unsigned m = __ballot_sync(0xFFFFFFFFu, in);
    int L = __ffs(m) - 1;

    unsigned dig = 0, r2 = 0;
    if (lane == L) {
        unsigned cum = excl;
        #pragma unroll 1
        for (int j = 0; j < PER; j++) {
            unsigned c = __ldcg(&h[lane * PER + j]);
            if (rank < cum + c) { dig = (unsigned)(lane * PER + j); r2 = rank - cum; break; }
            cum += c;
        }
    }
    dig = __shfl_sync(0xFFFFFFFFu, dig, L);
    r2  = __shfl_sync(0xFFFFFFFFu, r2,  L);
    *rem = r2;
    return dig;
}

// ---------------------------------------------------------------------------
// pass 0: histogram bits[31:21]. grid (HBLK, BATCH) x 256.
// Block = 16 contiguous rows (single band); thread = one float4 column;
// imp4 per-thread constant computed inline. Per-warp 4-replica smem hist
// (R7-proven banking: replica arrays 8KB apart, bin -> bank dig&31).
// Last block: select0, then zero g_hist[0] + reset counter for next replay.
// ---------------------------------------------------------------------------
__global__ void __launch_bounds__(256) hist0_kernel(const float4* __restrict__ coeffs,
                                                    const float* __restrict__ bi,
                                                    const float* __restrict__ di) {
    __shared__ unsigned sh[4][2048];
    __shared__ bool s_last;
    const int tid = threadIdx.x;
    const int warp = tid >> 5;

    for (int i = tid; i < 4 * 2048; i += 256) ((unsigned*)sh)[i] = 0;
    __syncthreads();

    const int batch = blockIdx.y;
    unsigned* h = sh[warp & 3];
    const int band = band_of(blockIdx.x << 4);
    const float4 imp = imp4_of(bi, di, band, tid << 2);
    const float4* p = coeffs + (size_t)batch * VEC_PB + (size_t)blockIdx.x * (16 * 256) + tid;

    #pragma unroll
    for (int r = 0; r < 16; r += 4) {
        float4 c0 = __ldg(p + (r + 0) * 256);
        float4 c1 = __ldg(p + (r + 1) * 256);
        float4 c2 = __ldg(p + (r + 2) * 256);
        float4 c3 = __ldg(p + (r + 3) * 256);
        atomicAdd(&h[__float_as_uint(imp.x * fabsf(c0.x)) >> 21], 1u);
        atomicAdd(&h[__float_as_uint(imp.y * fabsf(c0.y)) >> 21], 1u);
        atomicAdd(&h[__float_as_uint(imp.z * fabsf(c0.z)) >> 21], 1u);
        atomicAdd(&h[__float_as_uint(imp.w * fabsf(c0.w)) >> 21], 1u);
        atomicAdd(&h[__float_as_uint(imp.x * fabsf(c1.x)) >> 21], 1u);
        atomicAdd(&h[__float_as_uint(imp.y * fabsf(c1.y)) >> 21], 1u);
        atomicAdd(&h[__float_as_uint(imp.z * fabsf(c1.z)) >> 21], 1u);
        atomicAdd(&h[__float_as_uint(imp.w * fabsf(c1.w)) >> 21], 1u);
        atomicAdd(&h[__float_as_uint(imp.x * fabsf(c2.x)) >> 21], 1u);
        atomicAdd(&h[__float_as_uint(imp.y * fabsf(c2.y)) >> 21], 1u);
        atomicAdd(&h[__float_as_uint(imp.z * fabsf(c2.z)) >> 21], 1u);
        atomicAdd(&h[__float_as_uint(imp.w * fabsf(c2.w)) >> 21], 1u);
        atomicAdd(&h[__float_as_uint(imp.x * fabsf(c3.x)) >> 21], 1u);
        atomicAdd(&h[__float_as_uint(imp.y * fabsf(c3.y)) >> 21], 1u);
        atomicAdd(&h[__float_as_uint(imp.z * fabsf(c3.z)) >> 21], 1u);
        atomicAdd(&h[__float_as_uint(imp.w * fabsf(c3.w)) >> 21], 1u);
    }
    __syncthreads();

    for (int i = tid; i < 2048; i += 256) {
        unsigned s = sh[0][i] + sh[1][i] + sh[2][i] + sh[3][i];
        if (s) atomicAdd(&g_hist[0][batch][i], s);
    }

    // last-block-done: select0 for all batches, then restore zero state
    __threadfence();
    if (tid == 0) {
        unsigned done = atomicAdd(&g_done0, 1u);
        s_last = (done == HBLK * BATCH - 1);
    }
    __syncthreads();
    if (s_last) {
        __threadfence();
        const int b = tid >> 5;
        if (b < BATCH) {
            unsigned r1;
            unsigned d0 = warp_select<64>(g_hist[0][b], RANK0, &r1);
            if ((tid & 31) == 0) { g_d0[b] = d0; g_r1[b] = r1; }
        }
        __syncthreads();
        for (int i = tid; i < BATCH * 2048; i += 256) ((unsigned*)g_hist[0])[i] = 0;
        if (tid == 0) g_done0 = 0;
    }
}

// ---------------------------------------------------------------------------
// pass 1: histogram bits[20:10] among values with bits[31:21] == d0.
// Sparse updates -> 2 warp-replicas. Last block: select1 -> threshold
// (midpoint of 1024-ulp bin; measured end-to-end rel_err 3.2e-6), then
// restores zero state.
// ---------------------------------------------------------------------------
__global__ void __launch_bounds__(256) hist1_kernel(const float4* __restrict__ coeffs,
                                                    const float* __restrict__ bi,
                                                    const float* __restrict__ di) {
    __shared__ unsigned sh[2][2048];
    __shared__ bool s_last;
    const int tid = threadIdx.x;

    for (int i = tid; i < 2 * 2048; i += 256) ((unsigned*)sh)[i] = 0;
    __syncthreads();

    const int batch = blockIdx.y;
    const unsigned pref = g_d0[batch];
    unsigned* h = sh[(tid >> 5) & 1];
    const int band = band_of(blockIdx.x << 4);
    const float4 imp = imp4_of(bi, di, band, tid << 2);
    const float4* p = coeffs + (size_t)batch * VEC_PB + (size_t)blockIdx.x * (16 * 256) + tid;

    #pragma unroll
    for (int r = 0; r < 16; r += 4) {
        float4 c0 = __ldg(p + (r + 0) * 256);
        float4 c1 = __ldg(p + (r + 1) * 256);
        float4 c2 = __ldg(p + (r + 2) * 256);
        float4 c3 = __ldg(p + (r + 3) * 256);
        unsigned bb[16];
        bb[0]  = __float_as_uint(imp.x * fabsf(c0.x));
        bb[1]  = __float_as_uint(imp.y * fabsf(c0.y));
        bb[2]  = __float_as_uint(imp.z * fabsf(c0.z));
        bb[3]  = __float_as_uint(imp.w * fabsf(c0.w));
        bb[4]  = __float_as_uint(imp.x * fabsf(c1.x));
        bb[5]  = __float_as_uint(imp.y * fabsf(c1.y));
        bb[6]  = __float_as_uint(imp.z * fabsf(c1.z));
        bb[7]  = __float_as_uint(imp.w * fabsf(c1.w));
        bb[8]  = __float_as_uint(imp.x * fabsf(c2.x));
        bb[9]  = __float_as_uint(imp.y * fabsf(c2.y));
        bb[10] = __float_as_uint(imp.z * fabsf(c2.z));
        bb[11] = __float_as_uint(imp.w * fabsf(c2.w));
        bb[12] = __float_as_uint(imp.x * fabsf(c3.x));
        bb[13] = __float_as_uint(imp.y * fabsf(c3.y));
        bb[14] = __float_as_uint(imp.z * fabsf(c3.z));
        bb[15] = __float_as_uint(imp.w * fabsf(c3.w));
        #pragma unroll
        for (int j = 0; j < 16; j++)
            if ((bb[j] >> 21) == pref) atomicAdd(&h[(bb[j] >> 10) & 2047], 1u);
    }
    __syncthreads();

    for (int i = tid; i < 2048; i += 256) {
        unsigned s = sh[0][i] + sh[1][i];
        if (s) atomicAdd(&g_hist[1][batch][i], s);
    }

    // last-block-done: select1 -> threshold, then restore zero state
    __threadfence();
    if (tid == 0) {
        unsigned done = atomicAdd(&g_done1, 1u);
        s_last = (done == HBLK * BATCH - 1);
    }
    __syncthreads();
    if (s_last) {
        __threadfence();
        const int b = tid >> 5;
        if (b < BATCH) {
            unsigned r2;
            unsigned d1 = warp_select<64>(g_hist[1][b], g_r1[b], &r2);
            if ((tid & 31) == 0)
                g_thr[b] = __uint_as_float((g_d0[b] << 21) | (d1 << 10) | 512u);
        }
        __syncthreads();
        for (int i = tid; i < BATCH * 2048; i += 256) ((unsigned*)g_hist[1])[i] = 0;
        if (tid == 0) g_done1 = 0;
    }
}

// ---------------------------------------------------------------------------
// final: out[0..V)=coeffs*mask, out[V..2V)=mask, out[2V..3V)=importance.
// grid (FBLK, BATCH) x 256: 8 rows/block. imp4 per-thread constant computed
// inline and written from registers. Streaming stores for the 192MB writes.
// ---------------------------------------------------------------------------
__global__ void __launch_bounds__(256) final_kernel(const float4* __restrict__ coeffs,
                                                    const float* __restrict__ bi,
                                                    const float* __restrict__ di,
                                                    const float* __restrict__ temp,
                                                    float4* __restrict__ out) {
    const int tid = threadIdx.x;
    const int batch = blockIdx.y;
    const int band = band_of(blockIdx.x << 3);   // 8 rows/block; boundaries at mult of 8
    const float4 imp = imp4_of(bi, di, band, tid << 2);
    const float thr = g_thr[batch];
    const float inv_t = __frcp_rn(fabsf(__ldg(&temp[0])));

    const size_t vbase = (size_t)batch * VEC_PB + (size_t)blockIdx.x * (8 * 256) + tid;
    const float4* p = coeffs + vbase;

    #pragma unroll
    for (int r = 0; r < 8; r += 2) {
        float4 c0 = __ldg(p + (r + 0) * 256);
        float4 c1 = __ldg(p + (r + 1) * 256);

        float4 mk0, fl0, mk1, fl1;
        { float ci = imp.x * fabsf(c0.x); mk0.x = sigmoidf_fast((ci - thr) * inv_t); fl0.x = c0.x * mk0.x; }
        { float ci = imp.y * fabsf(c0.y); mk0.y = sigmoidf_fast((ci - thr) * inv_t); fl0.y = c0.y * mk0.y; }
        { float ci = imp.z * fabsf(c0.z); mk0.z = sigmoidf_fast((ci - thr) * inv_t); fl0.z = c0.z * mk0.z; }
        { float ci = imp.w * fabsf(c0.w); mk0.w = sigmoidf_fast((ci - thr) * inv_t); fl0.w = c0.w * mk0.w; }
        { float ci = imp.x * fabsf(c1.x); mk1.x = sigmoidf_fast((ci - thr) * inv_t); fl1.x = c1.x * mk1.x; }
        { float ci = imp.y * fabsf(c1.y); mk1.y = sigmoidf_fast((ci - thr) * inv_t); fl1.y = c1.y * mk1.y; }
        { float ci = imp.z * fabsf(c1.z); mk1.z = sigmoidf_fast((ci - thr) * inv_t); fl1.z = c1.z * mk1.z; }
        { float ci = imp.w * fabsf(c1.w); mk1.w = sigmoidf_fast((ci - thr) * inv_t); fl1.w = c1.w * mk1.w; }

        size_t ve0 = vbase + (size_t)(r + 0) * 256;
        size_t ve1 = vbase + (size_t)(r + 1) * 256;
        __stcs(&out[ve0], fl0);
        __stcs(&out[ve1], fl1);
        __stcs(&out[TOTALV + ve0], mk0);
        __stcs(&out[TOTALV + ve1], mk1);
        __stcs(&out[2 * TOTALV + ve0], imp);
        __stcs(&out[2 * TOTALV + ve1], imp);
    }
}

// ---------------------------------------------------------------------------
// launch — 3 kernels total
// ---------------------------------------------------------------------------
extern "C" void kernel_launch(void* const* d_in, const int* in_sizes, int n_in,
                              void* d_out, int out_size) {
    const float* coeffs = (const float*)d_in[0];
    const float* bi     = (const float*)d_in[1];
    const float* di     = (const float*)d_in[2];
    const float* temp   = (const float*)d_in[3];
    float* out = (float*)d_out;

    dim3 hg(HBLK, BATCH);
    hist0_kernel<<<hg, 256>>>((const float4*)coeffs, bi, di);
    hist1_kernel<<<hg, 256>>>((const float4*)coeffs, bi, di);

    dim3 fg(FBLK, BATCH);
    final_kernel<<<fg, 256>>>((const float4*)coeffs, bi, di, temp, (float4*)out);
}

// round 12
// speedup vs baseline: 1.3362x; 1.3362x over previous
#include <cuda_runtime.h>
#include <math.h>
#include <stdint.h>

// Problem constants
#define BATCH   8
#define SEQ     2048
#define HID     1024
#define NPB     (SEQ * HID)        // 2,097,152 elements per batch
#define VEC_PB  (NPB / 4)          // 524,288 float4 per batch
#define TOTALV  (BATCH * VEC_PB)   // 4,194,304 float4 total
#define RANK0   1048576u           // 0-indexed ascending rank of threshold (N - k)
#define NB0     8192               // pass-0 bins: bits[30:18] (sign always 0)
#define NB1     2048               // pass-1 bins: bits[17:7]
#define HBLK    128                // hist blocks per batch (16 rows each)
#define FBLK    256                // final blocks per batch (8 rows each)

// Static scratch (no runtime allocation allowed)
__device__ __align__(16) float g_imp5[5 * HID];   // sigmoid(band)*sigmoid(dim)
__device__ unsigned g_hist0[BATCH][NB0];          // 256 KB
__device__ unsigned g_hist1[BATCH][NB1];          // 64 KB
__device__ unsigned g_d0[BATCH];                  // selected 13-bit digit, pass 0
__device__ unsigned g_r1[BATCH];                  // remaining rank after pass 0
__device__ float    g_thr[BATCH];

__device__ __forceinline__ float sigmoidf_fast(float x) {
    return 1.0f / (1.0f + __expf(-x));
}

// band(t): 0 for t<128, else floor(log2(t>>7)) + 1   (T=2048, L=4)
__device__ __forceinline__ int band_of(int t) {
    return (t >= 128) ? (32 - __clz(t >> 7)) : 0;
}

// ---------------------------------------------------------------------------
// setup: zero both histograms, build importance table
// ---------------------------------------------------------------------------
__global__ void setup_kernel(const float* __restrict__ bi, const float* __restrict__ di) {
    int i = blockIdx.x * blockDim.x + threadIdx.x;
    if (i < BATCH * NB0) ((unsigned*)g_hist0)[i] = 0;
    if (i < BATCH * NB1) ((unsigned*)g_hist1)[i] = 0;
    if (i < 5 * HID) {
        float sb = sigmoidf_fast(bi[i]);
        float sd = sigmoidf_fast(di[i & (HID - 1)]);
        g_imp5[i] = sb * sd;
    }
}

// ---------------------------------------------------------------------------
// pass 0: histogram bits[30:18] (8192 bins; hot exponent mass spread over
// 32 mantissa sub-bins -> intra-warp atomic conflicts ~1-2 -> NO replicas).
// grid (HBLK, BATCH) x 256. Block = 16 contiguous rows (single band);
// thread = one float4 column -> imp4 is a per-thread constant.
// ---------------------------------------------------------------------------
__global__ void __launch_bounds__(256) hist0_kernel(const float4* __restrict__ coeffs) {
    __shared__ unsigned sh[NB0];                 // 32 KB
    const int tid = threadIdx.x;

    for (int i = tid; i < NB0; i += 256) sh[i] = 0;
    __syncthreads();

    const int batch = blockIdx.y;
    const int band = band_of(blockIdx.x << 4);
    const float4 imp = *reinterpret_cast<const float4*>(&g_imp5[band * HID + (tid << 2)]);
    const float4* p = coeffs + (size_t)batch * VEC_PB + (size_t)blockIdx.x * (16 * 256) + tid;

    #pragma unroll
    for (int r = 0; r < 16; r += 4) {
        float4 c0 = __ldg(p + (r + 0) * 256);
        float4 c1 = __ldg(p + (r + 1) * 256);
        float4 c2 = __ldg(p + (r + 2) * 256);
        float4 c3 = __ldg(p + (r + 3) * 256);
        atomicAdd(&sh[__float_as_uint(imp.x * fabsf(c0.x)) >> 18], 1u);
        atomicAdd(&sh[__float_as_uint(imp.y * fabsf(c0.y)) >> 18], 1u);
        atomicAdd(&sh[__float_as_uint(imp.z * fabsf(c0.z)) >> 18], 1u);
        atomicAdd(&sh[__float_as_uint(imp.w * fabsf(c0.w)) >> 18], 1u);
        atomicAdd(&sh[__float_as_uint(imp.x * fabsf(c1.x)) >> 18], 1u);
        atomicAdd(&sh[__float_as_uint(imp.y * fabsf(c1.y)) >> 18], 1u);
        atomicAdd(&sh[__float_as_uint(imp.z * fabsf(c1.z)) >> 18], 1u);
        atomicAdd(&sh[__float_as_uint(imp.w * fabsf(c1.w)) >> 18], 1u);
        atomicAdd(&sh[__float_as_uint(imp.x * fabsf(c2.x)) >> 18], 1u);
        atomicAdd(&sh[__float_as_uint(imp.y * fabsf(c2.y)) >> 18], 1u);
        atomicAdd(&sh[__float_as_uint(imp.z * fabsf(c2.z)) >> 18], 1u);
        atomicAdd(&sh[__float_as_uint(imp.w * fabsf(c2.w)) >> 18], 1u);
        atomicAdd(&sh[__float_as_uint(imp.x * fabsf(c3.x)) >> 18], 1u);
        atomicAdd(&sh[__float_as_uint(imp.y * fabsf(c3.y)) >> 18], 1u);
        atomicAdd(&sh[__float_as_uint(imp.z * fabsf(c3.z)) >> 18], 1u);
        atomicAdd(&sh[__float_as_uint(imp.w * fabsf(c3.w)) >> 18], 1u);
    }
    __syncthreads();

    unsigned* gh = g_hist0[batch];
    for (int i = tid; i < NB0; i += 256) {
        unsigned s = sh[i];
        if (s) atomicAdd(&gh[i], s);
    }
}

// ---------------------------------------------------------------------------
// select0: one block of 256 threads per batch over 8192 bins.
// thread t owns bins [t*32, t*32+32); block scan locates the rank.
// ---------------------------------------------------------------------------
__global__ void __launch_bounds__(256) select0_kernel() {
    __shared__ unsigned wtot[8];
    const int b = blockIdx.x;
    const int tid = threadIdx.x;
    const int lane = tid & 31;
    const int wid = tid >> 5;
    const unsigned* __restrict__ h = g_hist0[b];

    unsigned s = 0;
    #pragma unroll
    for (int j = 0; j < 32; j++) s += __ldcg(&h[tid * 32 + j]);

    // warp inclusive scan
    unsigned v = s;
    #pragma unroll
    for (int o = 1; o < 32; o <<= 1) {
        unsigned t = __shfl_up_sync(0xFFFFFFFFu, v, o);
        if (lane >= o) v += t;
    }
    if (lane == 31) wtot[wid] = v;
    __syncthreads();

    // scan the 8 warp totals (warp 0, lanes 0..7)
    if (wid == 0 && lane < 8) {
        unsigned t = wtot[lane];
        #pragma unroll
        for (int o = 1; o < 8; o <<= 1) {
            unsigned u = __shfl_up_sync(0xFFu, t, o);
            if (lane >= o) t += u;
        }
        wtot[lane] = t;   // inclusive
    }
    __syncthreads();

    unsigned excl = (wid ? wtot[wid - 1] : 0u) + (v - s);
    if (RANK0 >= excl && RANK0 < excl + s) {
        unsigned cum = excl;
        #pragma unroll 1
        for (int j = 0; j < 32; j++) {
            unsigned c = __ldcg(&h[tid * 32 + j]);
            if (RANK0 < cum + c) {
                g_d0[b] = (unsigned)(tid * 32 + j);
                g_r1[b] = RANK0 - cum;
                break;
            }
            cum += c;
        }
    }
}

// ---------------------------------------------------------------------------
// pass 1: histogram bits[17:7] among values with bits[30:18] == d0
// (~1% of data matches -> atomics negligible). Single smem hist, 8 KB.
// ---------------------------------------------------------------------------
__global__ void __launch_bounds__(256) hist1_kernel(const float4* __restrict__ coeffs) {
    __shared__ unsigned sh[NB1];
    const int tid = threadIdx.x;

    for (int i = tid; i < NB1; i += 256) sh[i] = 0;
    __syncthreads();

    const int batch = blockIdx.y;
    const unsigned pref = g_d0[batch];
    const int band = band_of(blockIdx.x << 4);
    const float4 imp = *reinterpret_cast<const float4*>(&g_imp5[band * HID + (tid << 2)]);
    const float4* p = coeffs + (size_t)batch * VEC_PB + (size_t)blockIdx.x * (16 * 256) + tid;

    #pragma unroll
    for (int r = 0; r < 16; r += 4) {
        float4 c0 = __ldg(p + (r + 0) * 256);
        float4 c1 = __ldg(p + (r + 1) * 256);
        float4 c2 = __ldg(p + (r + 2) * 256);
        float4 c3 = __ldg(p + (r + 3) * 256);
        unsigned bb[16];
        bb[0]  = __float_as_uint(imp.x * fabsf(c0.x));
        bb[1]  = __float_as_uint(imp.y * fabsf(c0.y));
        bb[2]  = __float_as_uint(imp.z * fabsf(c0.z));
        bb[3]  = __float_as_uint(imp.w * fabsf(c0.w));
        bb[4]  = __float_as_uint(imp.x * fabsf(c1.x));
        bb[5]  = __float_as_uint(imp.y * fabsf(c1.y));
        bb[6]  = __float_as_uint(imp.z * fabsf(c1.z));
        bb[7]  = __float_as_uint(imp.w * fabsf(c1.w));
        bb[8]  = __float_as_uint(imp.x * fabsf(c2.x));
        bb[9]  = __float_as_uint(imp.y * fabsf(c2.y));
        bb[10] = __float_as_uint(imp.z * fabsf(c2.z));
        bb[11] = __float_as_uint(imp.w * fabsf(c2.w));
        bb[12] = __float_as_uint(imp.x * fabsf(c3.x));
        bb[13] = __float_as_uint(imp.y * fabsf(c3.y));
        bb[14] = __float_as_uint(imp.z * fabsf(c3.z));
        bb[15] = __float_as_uint(imp.w * fabsf(c3.w));
        #pragma unroll
        for (int j = 0; j < 16; j++)
            if ((bb[j] >> 18) == pref) atomicAdd(&sh[(bb[j] >> 7) & (NB1 - 1)], 1u);
    }
    __syncthreads();

    unsigned* gh = g_hist1[batch];
    for (int i = tid; i < NB1; i += 256) {
        unsigned s = sh[i];
        if (s) atomicAdd(&gh[i], s);
    }
}

// ---------------------------------------------------------------------------
// select1: one warp per batch over 2048 bins; threshold = midpoint of the
// resolved 128-ulp bin (rel err <= 2^-17).
// ---------------------------------------------------------------------------
__global__ void __launch_bounds__(256) select1_kernel() {
    const int b = threadIdx.x >> 5;
    if (b >= BATCH) return;
    const int lane = threadIdx.x & 31;
    const unsigned* __restrict__ h = g_hist1[b];
    const unsigned rank = g_r1[b];

    unsigned s = 0;
    #pragma unroll
    for (int j = 0; j < 64; j++) s += __ldcg(&h[lane * 64 + j]);

    unsigned v = s;
    #pragma unroll
    for (int o = 1; o < 32; o <<= 1) {
        unsigned t = __shfl_up_sync(0xFFFFFFFFu, v, o);
        if (lane >= o) v += t;
    }
    unsigned excl = v - s;

    if (rank >= excl && rank < excl + s) {
        unsigned cum = excl;
        #pragma unroll 1
        for (int j = 0; j < 64; j++) {
            unsigned c = __ldcg(&h[lane * 64 + j]);
            if (rank < cum + c) {
                unsigned d1 = (unsigned)(lane * 64 + j);
                g_thr[b] = __uint_as_float((g_d0[b] << 18) | (d1 << 7) | 64u);
                break;
            }
            cum += c;
        }
    }
}

// ---------------------------------------------------------------------------
// final: out[0..V)=coeffs*mask, out[V..2V)=mask, out[2V..3V)=importance.
// grid (FBLK, BATCH) x 256: 8 rows/block. imp4 per-thread constant, written
// from registers. Streaming stores for the 192MB write side.
// ---------------------------------------------------------------------------
__global__ void __launch_bounds__(256) final_kernel(const float4* __restrict__ coeffs,
                                                    const float* __restrict__ temp,
                                                    float4* __restrict__ out) {
    const int tid = threadIdx.x;
    const int batch = blockIdx.y;
    const int band = band_of(blockIdx.x << 3);   // 8 rows/block
    const float4 imp = *reinterpret_cast<const float4*>(&g_imp5[band * HID + (tid << 2)]);
    const float thr = g_thr[batch];
    const float inv_t = __frcp_rn(fabsf(__ldg(&temp[0])));

    const size_t vbase = (size_t)batch * VEC_PB + (size_t)blockIdx.x * (8 * 256) + tid;
    const float4* p = coeffs + vbase;

    #pragma unroll
    for (int r = 0; r < 8; r += 2) {
        float4 c0 = __ldg(p + (r + 0) * 256);
        float4 c1 = __ldg(p + (r + 1) * 256);

        float4 mk0, fl0, mk1, fl1;
        { float ci = imp.x * fabsf(c0.x); mk0.x = sigmoidf_fast((ci - thr) * inv_t); fl0.x = c0.x * mk0.x; }
        { float ci = imp.y * fabsf(c0.y); mk0.y = sigmoidf_fast((ci - thr) * inv_t); fl0.y = c0.y * mk0.y; }
        { float ci = imp.z * fabsf(c0.z); mk0.z = sigmoidf_fast((ci - thr) * inv_t); fl0.z = c0.z * mk0.z; }
        { float ci = imp.w * fabsf(c0.w); mk0.w = sigmoidf_fast((ci - thr) * inv_t); fl0.w = c0.w * mk0.w; }
        { float ci = imp.x * fabsf(c1.x); mk1.x = sigmoidf_fast((ci - thr) * inv_t); fl1.x = c1.x * mk1.x; }
        { float ci = imp.y * fabsf(c1.y); mk1.y = sigmoidf_fast((ci - thr) * inv_t); fl1.y = c1.y * mk1.y; }
        { float ci = imp.z * fabsf(c1.z); mk1.z = sigmoidf_fast((ci - thr) * inv_t); fl1.z = c1.z * mk1.z; }
        { float ci = imp.w * fabsf(c1.w); mk1.w = sigmoidf_fast((ci - thr) * inv_t); fl1.w = c1.w * mk1.w; }

        size_t ve0 = vbase + (size_t)(r + 0) * 256;
        size_t ve1 = vbase + (size_t)(r + 1) * 256;
        __stcs(&out[ve0], fl0);
        __stcs(&out[ve1], fl1);
        __stcs(&out[TOTALV + ve0], mk0);
        __stcs(&out[TOTALV + ve1], mk1);
        __stcs(&out[2 * TOTALV + ve0], imp);
        __stcs(&out[2 * TOTALV + ve1], imp);
    }
}

// ---------------------------------------------------------------------------
// launch
// ---------------------------------------------------------------------------
extern "C" void kernel_launch(void* const* d_in, const int* in_sizes, int n_in,
                              void* d_out, int out_size) {
    const float* coeffs = (const float*)d_in[0];
    const float* bi     = (const float*)d_in[1];
    const float* di     = (const float*)d_in[2];
    const float* temp   = (const float*)d_in[3];
    float* out = (float*)d_out;

    setup_kernel<<<(BATCH * NB0 + 255) / 256, 256>>>(bi, di);

    dim3 hg(HBLK, BATCH);
    hist0_kernel<<<hg, 256>>>((const float4*)coeffs);
    select0_kernel<<<BATCH, 256>>>();
    hist1_kernel<<<hg, 256>>>((const float4*)coeffs);
    select1_kernel<<<1, 256>>>();

    dim3 fg(FBLK, BATCH);
    final_kernel<<<fg, 256>>>((const float4*)coeffs, temp, (float4*)out);
}